// round 11
// baseline (speedup 1.0000x reference)
#include <cuda_runtime.h>
#include <math.h>

#define NUM_NODES   2000000
#define NUM_MOVABLE 1500000
#define NUM_FILLER  400000
#define NUM_NETS    1500000
#define NUM_PINS    6000000
#define NB          512
#define NBP         513          // padded dim for diff map
#define BIN_W       1.953125f
#define UNIT_CAP    1.5f
#define EPSF        1e-6f

// ---------------- scratch (static device globals; no allocations) -----------
__device__ float2 g_pin_xy[NUM_PINS];   // interleaved (x,y) per physical pin
__device__ float2 g_D[NBP * NBP];       // diff map [y*NBP + x], padded
__device__ float2 g_Sf[NB * NB];        // scan_x result [y*NB + x] (float2)
__device__ float  g_ratio[NB * NB];     // ratio map [x*NB + y]
__device__ float  g_binarea[NB * NB];   // per-bin movable area [x*NB + y]
__device__ double g_sum_area;
__device__ double g_sum_route;
__device__ double g_sum_filler;

__device__ __forceinline__ int bin_of(float v) {
    int b = (int)floorf(v / BIN_W);
    return min(max(b, 0), NB - 1);
}

// one L2 atomic op for the adjacent (dh, dv) pair
__device__ __forceinline__ void red2(float2* addr, float a, float b) {
    asm volatile("red.global.add.v2.f32 [%0], {%1, %2};"
                 :: "l"(addr), "f"(a), "f"(b) : "memory");
}

// ---------------- kernel 1: pin transpose + zero scratch --------------------
#define PIN_GROUPS (NUM_PINS / 4)          // 1.5M
__global__ void k_prep(const float4* __restrict__ px4,
                       const float4* __restrict__ py4) {
    int g = blockIdx.x * blockDim.x + threadIdx.x;
    if (g < PIN_GROUPS) {
        float4 x = px4[g];
        float4 y = py4[g];
        float4* out = (float4*)g_pin_xy;
        out[g * 2]     = make_float4(x.x, y.x, x.y, y.y);
        out[g * 2 + 1] = make_float4(x.z, y.z, x.w, y.w);
    }
    if (g < NBP * NBP) g_D[g] = make_float2(0.0f, 0.0f);
    if (g < NB * NB)   g_binarea[g] = 0.0f;
    if (g == 0) {
        g_sum_area   = 0.0;
        g_sum_route  = 0.0;
        g_sum_filler = 0.0;
    }
}

// ---------------- kernel 2: fused nets-scatter + node sums ------------------
#define NET_PER_THREAD 4
#define NET_THREADS    (NUM_NETS / NET_PER_THREAD)          // 375000
#define NET_BLOCKS     ((NET_THREADS + 255) / 256)          // 1465
#define AREA_GROUPS    (NUM_NODES / 4)                      // 500000
#define AREA_BLOCKS    ((AREA_GROUPS + 255) / 256)          // 1954

// compute bbox corners + values from 4 already-loaded pins, then scatter
__device__ __forceinline__ void net_scatter_vals(float2 p0, float2 p1,
                                                 float2 p2, float2 p3) {
    float xl = fminf(fminf(p0.x, p1.x), fminf(p2.x, p3.x));
    float xh = fmaxf(fmaxf(p0.x, p1.x), fmaxf(p2.x, p3.x));
    float yl = fminf(fminf(p0.y, p1.y), fminf(p2.y, p3.y));
    float yh = fmaxf(fmaxf(p0.y, p1.y), fmaxf(p2.y, p3.y));

    float bw = xh - xl;
    float bh = yh - yl;
    float barea = fmaxf(bw * bh, EPSF);
    float dh = bw / barea;
    float dv = bh / barea;

    int blx = bin_of(xl);
    int bhx = bin_of(xh) + 1;   // up to 512: lands in padding (never read)
    int bly = bin_of(yl);
    int bhy = bin_of(yh) + 1;

    red2(&g_D[bly * NBP + blx],  dh,  dv);
    red2(&g_D[bly * NBP + bhx], -dh, -dv);
    red2(&g_D[bhy * NBP + blx], -dh, -dv);
    red2(&g_D[bhy * NBP + bhx],  dh,  dv);
}

__global__ void k_fused(const int* __restrict__ flat_netpin,
                        const float4* __restrict__ pos4,
                        const float4* __restrict__ posy4,
                        const float4* __restrict__ nsx4,
                        const float4* __restrict__ nsy4) {
    if (blockIdx.x < NET_BLOCKS) {
        int gid = blockIdx.x * blockDim.x + threadIdx.x;
        int n0 = gid * NET_PER_THREAD;
        if (n0 >= NUM_NETS) return;
        const int4* fp4 = (const int4*)flat_netpin;
        int4 fa = __ldg(&fp4[n0]);
        int4 fb = __ldg(&fp4[n0 + 1]);
        int4 fc = __ldg(&fp4[n0 + 2]);
        int4 fd = __ldg(&fp4[n0 + 3]);

        // phase 1: issue all 16 gathers before any atomic (max MLP)
        float2 a0 = __ldg(&g_pin_xy[fa.x]), a1 = __ldg(&g_pin_xy[fa.y]);
        float2 a2 = __ldg(&g_pin_xy[fa.z]), a3 = __ldg(&g_pin_xy[fa.w]);
        float2 b0 = __ldg(&g_pin_xy[fb.x]), b1 = __ldg(&g_pin_xy[fb.y]);
        float2 b2 = __ldg(&g_pin_xy[fb.z]), b3 = __ldg(&g_pin_xy[fb.w]);
        float2 c0 = __ldg(&g_pin_xy[fc.x]), c1 = __ldg(&g_pin_xy[fc.y]);
        float2 c2 = __ldg(&g_pin_xy[fc.z]), c3 = __ldg(&g_pin_xy[fc.w]);
        float2 d0 = __ldg(&g_pin_xy[fd.x]), d1 = __ldg(&g_pin_xy[fd.y]);
        float2 d2 = __ldg(&g_pin_xy[fd.z]), d3 = __ldg(&g_pin_xy[fd.w]);

        // phase 2: compute + scatter
        net_scatter_vals(a0, a1, a2, a3);
        net_scatter_vals(b0, b1, b2, b3);
        net_scatter_vals(c0, c1, c2, c3);
        net_scatter_vals(d0, d1, d2, d3);
        return;
    }

    // ---- area part ----
    int g = (blockIdx.x - NET_BLOCKS) * blockDim.x + threadIdx.x;
    double la = 0.0, lf = 0.0;
    if (g < AREA_GROUPS) {
        int i0 = g * 4;
        float4 sx = nsx4[g];
        float4 sy = nsy4[g];
        if (i0 < NUM_MOVABLE) {
            float4 px = pos4[g];
            float4 py = posy4[g];
            float a0 = sx.x * sy.x, a1 = sx.y * sy.y;
            float a2 = sx.z * sy.z, a3 = sx.w * sy.w;
            int b0 = bin_of(px.x + 0.5f * sx.x) * NB + bin_of(py.x + 0.5f * sy.x);
            int b1 = bin_of(px.y + 0.5f * sx.y) * NB + bin_of(py.y + 0.5f * sy.y);
            int b2 = bin_of(px.z + 0.5f * sx.z) * NB + bin_of(py.z + 0.5f * sy.z);
            int b3 = bin_of(px.w + 0.5f * sx.w) * NB + bin_of(py.w + 0.5f * sy.w);
            atomicAdd(&g_binarea[b0], a0);
            atomicAdd(&g_binarea[b1], a1);
            atomicAdd(&g_binarea[b2], a2);
            atomicAdd(&g_binarea[b3], a3);
            la = (double)a0 + (double)a1 + (double)a2 + (double)a3;
        } else if (i0 >= NUM_NODES - NUM_FILLER) {
            lf = (double)(sx.x * sy.x) + (double)(sx.y * sy.y)
               + (double)(sx.z * sy.z) + (double)(sx.w * sy.w);
        }
    }
    for (int off = 16; off > 0; off >>= 1) {
        la += __shfl_down_sync(0xFFFFFFFFu, la, off);
        lf += __shfl_down_sync(0xFFFFFFFFu, lf, off);
    }
    if ((threadIdx.x & 31) == 0) {
        if (la != 0.0) atomicAdd(&g_sum_area,   la);
        if (lf != 0.0) atomicAdd(&g_sum_filler, lf);
    }
}

// ---------------- block-wide inclusive scan (512 threads, double2) ----------
__device__ __forceinline__ double2 block_scan_512(double2 v) {
    __shared__ double2 partials[16];
    int lane = threadIdx.x & 31;
    int warp = threadIdx.x >> 5;
    #pragma unroll
    for (int off = 1; off < 32; off <<= 1) {
        double ax = __shfl_up_sync(0xFFFFFFFFu, v.x, off);
        double ay = __shfl_up_sync(0xFFFFFFFFu, v.y, off);
        if (lane >= off) { v.x += ax; v.y += ay; }
    }
    if (lane == 31) partials[warp] = v;
    __syncthreads();
    if (warp == 0 && lane < 16) {
        double2 p = partials[lane];
        #pragma unroll
        for (int off = 1; off < 16; off <<= 1) {
            double ax = __shfl_up_sync(0x0000FFFFu, p.x, off);
            double ay = __shfl_up_sync(0x0000FFFFu, p.y, off);
            if (lane >= off) { p.x += ax; p.y += ay; }
        }
        partials[lane] = p;
    }
    __syncthreads();
    if (warp > 0) {
        double2 p = partials[warp - 1];
        v.x += p.x; v.y += p.y;
    }
    return v;
}

// ---------------- kernel 3: inclusive scan along x (fully coalesced) --------
__global__ void k_scan_x() {
    int y = blockIdx.x;
    int x = threadIdx.x;
    float2 d = g_D[y * NBP + x];
    double2 v = make_double2((double)d.x, (double)d.y);
    v = block_scan_512(v);
    g_Sf[y * NB + x] = make_float2((float)v.x, (float)v.y);
}

// ---------------- kernel 4: scan along y + ratio + dot ----------------------
__global__ void k_scan_y_ratio() {
    __shared__ double s_route[16];
    int x = blockIdx.x;
    int y = threadIdx.x;
    int lane = threadIdx.x & 31;
    int warp = threadIdx.x >> 5;

    float2 d = g_Sf[y * NB + x];
    double2 v = make_double2((double)d.x, (double)d.y);
    v = block_scan_512(v);
    float uh = (float)v.x / UNIT_CAP;
    float uv = (float)v.y / UNIT_CAP;
    float r = fminf(fmaxf(fmaxf(uh, uv), 0.5f), 2.0f);
    int idx = x * NB + y;
    g_ratio[idx] = r;

    // fused dot(ratio, binarea) for sum_route
    double lr = (double)(r * g_binarea[idx]);
    for (int off = 16; off > 0; off >>= 1)
        lr += __shfl_down_sync(0xFFFFFFFFu, lr, off);
    if (lane == 0) s_route[warp] = lr;
    __syncthreads();
    if (warp == 0) {
        double t = (lane < 16) ? s_route[lane] : 0.0;
        for (int off = 8; off > 0; off >>= 1)
            t += __shfl_down_sync(0xFFFFFFFFu, t, off);
        if (lane == 0 && t != 0.0) atomicAdd(&g_sum_route, t);
    }
}

// ---------------- kernel 5: outputs (float4, inline scalars) ----------------
__global__ void k_output(const float4* __restrict__ pos4,
                         const float4* __restrict__ posy4,
                         const float4* __restrict__ nsx4,
                         const float4* __restrict__ nsy4,
                         float4* __restrict__ out) {
    int g = blockIdx.x * blockDim.x + threadIdx.x;
    if (g >= NUM_NODES / 4) return;
    int i0 = g * 4;

    // scalars from global sums (uniform broadcast loads)
    float sum_area   = (float)g_sum_area;
    float sum_route  = (float)g_sum_route;
    float sum_filler = (float)g_sum_filler;
    float max_total  = sum_area + sum_filler;
    float scale  = fminf(1.0f, max_total / fmaxf(sum_route, EPSF));
    float fscale = sqrtf(fmaxf(max_total - sum_route * scale, 0.0f) /
                         fmaxf(sum_filler, EPSF));

    float4 x  = pos4[g];
    float4 y  = posy4[g];
    float4 sx = nsx4[g];
    float4 sy = nsy4[g];

    float4 xo = x, yo = y, sxo = sx, syo = sy;

    if (i0 < NUM_MOVABLE) {
        {
            float r = g_ratio[bin_of(x.x + 0.5f * sx.x) * NB + bin_of(y.x + 0.5f * sy.x)];
            float sr = sqrtf(r * scale);
            float nx = sx.x * sr, ny = sy.x * sr;
            xo.x = x.x + 0.5f * (sx.x - nx); yo.x = y.x + 0.5f * (sy.x - ny);
            sxo.x = nx; syo.x = ny;
        }
        {
            float r = g_ratio[bin_of(x.y + 0.5f * sx.y) * NB + bin_of(y.y + 0.5f * sy.y)];
            float sr = sqrtf(r * scale);
            float nx = sx.y * sr, ny = sy.y * sr;
            xo.y = x.y + 0.5f * (sx.y - nx); yo.y = y.y + 0.5f * (sy.y - ny);
            sxo.y = nx; syo.y = ny;
        }
        {
            float r = g_ratio[bin_of(x.z + 0.5f * sx.z) * NB + bin_of(y.z + 0.5f * sy.z)];
            float sr = sqrtf(r * scale);
            float nx = sx.z * sr, ny = sy.z * sr;
            xo.z = x.z + 0.5f * (sx.z - nx); yo.z = y.z + 0.5f * (sy.z - ny);
            sxo.z = nx; syo.z = ny;
        }
        {
            float r = g_ratio[bin_of(x.w + 0.5f * sx.w) * NB + bin_of(y.w + 0.5f * sy.w)];
            float sr = sqrtf(r * scale);
            float nx = sx.w * sr, ny = sy.w * sr;
            xo.w = x.w + 0.5f * (sx.w - nx); yo.w = y.w + 0.5f * (sy.w - ny);
            sxo.w = nx; syo.w = ny;
        }
    } else if (i0 >= NUM_NODES - NUM_FILLER) {
        sxo.x = sx.x * fscale; sxo.y = sx.y * fscale;
        sxo.z = sx.z * fscale; sxo.w = sx.w * fscale;
        syo.x = sy.x * fscale; syo.y = sy.y * fscale;
        syo.z = sy.z * fscale; syo.w = sy.w * fscale;
    }

    const int Q = NUM_NODES / 4;
    out[g]         = xo;
    out[Q + g]     = yo;
    out[2 * Q + g] = sxo;
    out[3 * Q + g] = syo;
}

// ---------------- launch -----------------------------------------------------
extern "C" void kernel_launch(void* const* d_in, const int* in_sizes, int n_in,
                              void* d_out, int out_size) {
    const float* pos         = (const float*)d_in[0];
    const float* pin_pos     = (const float*)d_in[1];
    const float* node_size_x = (const float*)d_in[2];
    const float* node_size_y = (const float*)d_in[3];
    const int*   flat_netpin = (const int*)d_in[4];
    float* out = (float*)d_out;

    const float4* pos4  = (const float4*)pos;
    const float4* posy4 = (const float4*)(pos + NUM_NODES);
    const float4* nsx4  = (const float4*)node_size_x;
    const float4* nsy4  = (const float4*)node_size_y;
    const float4* px4   = (const float4*)pin_pos;
    const float4* py4   = (const float4*)(pin_pos + NUM_PINS);

    const int Q = NUM_NODES / 4;

    k_prep<<<(PIN_GROUPS + 255) / 256, 256>>>(px4, py4);
    k_fused<<<NET_BLOCKS + AREA_BLOCKS, 256>>>(flat_netpin,
                                               pos4, posy4, nsx4, nsy4);
    k_scan_x<<<NB, NB>>>();
    k_scan_y_ratio<<<NB, NB>>>();
    k_output<<<(Q + 255) / 256, 256>>>(pos4, posy4, nsx4, nsy4, (float4*)out);
}

// round 12
// speedup vs baseline: 1.0017x; 1.0017x over previous
#include <cuda_runtime.h>
#include <math.h>

#define NUM_NODES   2000000
#define NUM_MOVABLE 1500000
#define NUM_FILLER  400000
#define NUM_NETS    1500000
#define NUM_PINS    6000000
#define NB          512
#define NBP         513          // padded dim for diff map
#define BIN_W       1.953125f
#define UNIT_CAP    1.5f
#define EPSF        1e-6f

// ---------------- scratch (static device globals; no allocations) -----------
__device__ float2 g_pin_xy[NUM_PINS];   // interleaved (x,y) per physical pin
__device__ float2 g_D[NBP * NBP];       // diff map [y*NBP + x], padded
__device__ float2 g_Sf[NB * NB];        // scan_x result [y*NB + x] (float2)
__device__ float  g_ratio[NB * NB];     // ratio map [x*NB + y]
__device__ float  g_binarea[NB * NB];   // per-bin movable area [x*NB + y]
__device__ double g_sum_area;
__device__ double g_sum_route;
__device__ double g_sum_filler;
__device__ unsigned int g_bar;          // device-wide barrier counter

__device__ __forceinline__ int bin_of(float v) {
    int b = (int)floorf(v / BIN_W);
    return min(max(b, 0), NB - 1);
}

// one L2 atomic op for the adjacent (dh, dv) pair
__device__ __forceinline__ void red2(float2* addr, float a, float b) {
    asm volatile("red.global.add.v2.f32 [%0], {%1, %2};"
                 :: "l"(addr), "f"(a), "f"(b) : "memory");
}

// ---------------- kernel 1: pin transpose + zero scratch --------------------
#define PIN_GROUPS (NUM_PINS / 4)          // 1.5M
__global__ void k_prep(const float4* __restrict__ px4,
                       const float4* __restrict__ py4) {
    int g = blockIdx.x * blockDim.x + threadIdx.x;
    if (g < PIN_GROUPS) {
        float4 x = px4[g];
        float4 y = py4[g];
        float4* out = (float4*)g_pin_xy;
        out[g * 2]     = make_float4(x.x, y.x, x.y, y.y);
        out[g * 2 + 1] = make_float4(x.z, y.z, x.w, y.w);
    }
    if (g < NBP * NBP) g_D[g] = make_float2(0.0f, 0.0f);
    if (g < NB * NB)   g_binarea[g] = 0.0f;
    if (g == 0) {
        g_sum_area   = 0.0;
        g_sum_route  = 0.0;
        g_sum_filler = 0.0;
        g_bar        = 0u;
    }
}

// ---------------- kernel 2: fused nets-scatter + node sums ------------------
#define NET_PER_THREAD 2
#define NET_THREADS    (NUM_NETS / NET_PER_THREAD)          // 750000
#define NET_BLOCKS     ((NET_THREADS + 255) / 256)          // 2930
#define AREA_GROUPS    (NUM_NODES / 4)                      // 500000
#define AREA_BLOCKS    ((AREA_GROUPS + 255) / 256)          // 1954

__device__ __forceinline__ void net_scatter(int4 fp) {
    float2 p0 = __ldg(&g_pin_xy[fp.x]);
    float2 p1 = __ldg(&g_pin_xy[fp.y]);
    float2 p2 = __ldg(&g_pin_xy[fp.z]);
    float2 p3 = __ldg(&g_pin_xy[fp.w]);

    float xl = fminf(fminf(p0.x, p1.x), fminf(p2.x, p3.x));
    float xh = fmaxf(fmaxf(p0.x, p1.x), fmaxf(p2.x, p3.x));
    float yl = fminf(fminf(p0.y, p1.y), fminf(p2.y, p3.y));
    float yh = fmaxf(fmaxf(p0.y, p1.y), fmaxf(p2.y, p3.y));

    float bw = xh - xl;
    float bh = yh - yl;
    float barea = fmaxf(bw * bh, EPSF);
    float dh = bw / barea;
    float dv = bh / barea;

    int blx = bin_of(xl);
    int bhx = bin_of(xh) + 1;   // up to 512: lands in padding (never read)
    int bly = bin_of(yl);
    int bhy = bin_of(yh) + 1;

    red2(&g_D[bly * NBP + blx],  dh,  dv);
    red2(&g_D[bly * NBP + bhx], -dh, -dv);
    red2(&g_D[bhy * NBP + blx], -dh, -dv);
    red2(&g_D[bhy * NBP + bhx],  dh,  dv);
}

__global__ void k_fused(const int* __restrict__ flat_netpin,
                        const float4* __restrict__ pos4,
                        const float4* __restrict__ posy4,
                        const float4* __restrict__ nsx4,
                        const float4* __restrict__ nsy4) {
    if (blockIdx.x < NET_BLOCKS) {
        int gid = blockIdx.x * blockDim.x + threadIdx.x;
        int n0 = gid * NET_PER_THREAD;
        if (n0 >= NUM_NETS) return;
        const int4* fp4 = (const int4*)flat_netpin;
        int4 a = fp4[n0];
        int4 b = fp4[n0 + 1];
        net_scatter(a);
        net_scatter(b);
        return;
    }

    // ---- area part ----
    int g = (blockIdx.x - NET_BLOCKS) * blockDim.x + threadIdx.x;
    double la = 0.0, lf = 0.0;
    if (g < AREA_GROUPS) {
        int i0 = g * 4;
        float4 sx = nsx4[g];
        float4 sy = nsy4[g];
        if (i0 < NUM_MOVABLE) {
            float4 px = pos4[g];
            float4 py = posy4[g];
            float a0 = sx.x * sy.x, a1 = sx.y * sy.y;
            float a2 = sx.z * sy.z, a3 = sx.w * sy.w;
            int b0 = bin_of(px.x + 0.5f * sx.x) * NB + bin_of(py.x + 0.5f * sy.x);
            int b1 = bin_of(px.y + 0.5f * sx.y) * NB + bin_of(py.y + 0.5f * sy.y);
            int b2 = bin_of(px.z + 0.5f * sx.z) * NB + bin_of(py.z + 0.5f * sy.z);
            int b3 = bin_of(px.w + 0.5f * sx.w) * NB + bin_of(py.w + 0.5f * sy.w);
            atomicAdd(&g_binarea[b0], a0);
            atomicAdd(&g_binarea[b1], a1);
            atomicAdd(&g_binarea[b2], a2);
            atomicAdd(&g_binarea[b3], a3);
            la = (double)a0 + (double)a1 + (double)a2 + (double)a3;
        } else if (i0 >= NUM_NODES - NUM_FILLER) {
            lf = (double)(sx.x * sy.x) + (double)(sx.y * sy.y)
               + (double)(sx.z * sy.z) + (double)(sx.w * sy.w);
        }
    }
    for (int off = 16; off > 0; off >>= 1) {
        la += __shfl_down_sync(0xFFFFFFFFu, la, off);
        lf += __shfl_down_sync(0xFFFFFFFFu, lf, off);
    }
    if ((threadIdx.x & 31) == 0) {
        if (la != 0.0) atomicAdd(&g_sum_area,   la);
        if (lf != 0.0) atomicAdd(&g_sum_filler, lf);
    }
}

// ---------------- block-wide inclusive scan (512 threads, double2) ----------
__device__ __forceinline__ double2 block_scan_512(double2 v) {
    __shared__ double2 partials[16];
    int lane = threadIdx.x & 31;
    int warp = threadIdx.x >> 5;
    #pragma unroll
    for (int off = 1; off < 32; off <<= 1) {
        double ax = __shfl_up_sync(0xFFFFFFFFu, v.x, off);
        double ay = __shfl_up_sync(0xFFFFFFFFu, v.y, off);
        if (lane >= off) { v.x += ax; v.y += ay; }
    }
    if (lane == 31) partials[warp] = v;
    __syncthreads();
    if (warp == 0 && lane < 16) {
        double2 p = partials[lane];
        #pragma unroll
        for (int off = 1; off < 16; off <<= 1) {
            double ax = __shfl_up_sync(0x0000FFFFu, p.x, off);
            double ay = __shfl_up_sync(0x0000FFFFu, p.y, off);
            if (lane >= off) { p.x += ax; p.y += ay; }
        }
        partials[lane] = p;
    }
    __syncthreads();
    if (warp > 0) {
        double2 p = partials[warp - 1];
        v.x += p.x; v.y += p.y;
    }
    return v;
}

// ---------------- kernel 3: merged scan_x + scan_y (one wave + barrier) -----
// 512 blocks x 512 threads, __launch_bounds__ caps regs at 32 so 4 blocks/SM
// -> 592 resident slots >= 512 blocks: all blocks co-resident, spin barrier safe.
__global__ void __launch_bounds__(512, 4) k_scan() {
    int b = blockIdx.x;
    int t = threadIdx.x;

    // ---- phase 1: inclusive scan along x for row y=b (fully coalesced) ----
    {
        float2 d = g_D[b * NBP + t];
        double2 v = make_double2((double)d.x, (double)d.y);
        v = block_scan_512(v);
        g_Sf[b * NB + t] = make_float2((float)v.x, (float)v.y);
    }
    __syncthreads();

    // ---- device-wide barrier (threadfence-reduction pattern) ----
    if (t == 0) {
        __threadfence();
        atomicAdd(&g_bar, 1u);
        while (atomicAdd(&g_bar, 0u) < NB) __nanosleep(64);
        __threadfence();
    }
    __syncthreads();

    // ---- phase 2: scan along y for column x=b + ratio + dot ----
    {
        __shared__ double s_route[16];
        int x = b;
        int y = t;
        int lane = t & 31;
        int warp = t >> 5;

        float2 d = g_Sf[y * NB + x];
        double2 v = make_double2((double)d.x, (double)d.y);
        v = block_scan_512(v);
        float uh = (float)v.x / UNIT_CAP;
        float uv = (float)v.y / UNIT_CAP;
        float r = fminf(fmaxf(fmaxf(uh, uv), 0.5f), 2.0f);
        int idx = x * NB + y;
        g_ratio[idx] = r;

        double lr = (double)(r * g_binarea[idx]);
        for (int off = 16; off > 0; off >>= 1)
            lr += __shfl_down_sync(0xFFFFFFFFu, lr, off);
        if (lane == 0) s_route[warp] = lr;
        __syncthreads();
        if (warp == 0) {
            double tt = (lane < 16) ? s_route[lane] : 0.0;
            for (int off = 8; off > 0; off >>= 1)
                tt += __shfl_down_sync(0xFFFFFFFFu, tt, off);
            if (lane == 0 && tt != 0.0) atomicAdd(&g_sum_route, tt);
        }
    }
}

// ---------------- kernel 4: outputs (float4, inline scalars) ----------------
__global__ void k_output(const float4* __restrict__ pos4,
                         const float4* __restrict__ posy4,
                         const float4* __restrict__ nsx4,
                         const float4* __restrict__ nsy4,
                         float4* __restrict__ out) {
    int g = blockIdx.x * blockDim.x + threadIdx.x;
    if (g >= NUM_NODES / 4) return;
    int i0 = g * 4;

    // scalars from global sums (uniform broadcast loads)
    float sum_area   = (float)g_sum_area;
    float sum_route  = (float)g_sum_route;
    float sum_filler = (float)g_sum_filler;
    float max_total  = sum_area + sum_filler;
    float scale  = fminf(1.0f, max_total / fmaxf(sum_route, EPSF));
    float fscale = sqrtf(fmaxf(max_total - sum_route * scale, 0.0f) /
                         fmaxf(sum_filler, EPSF));

    float4 x  = pos4[g];
    float4 y  = posy4[g];
    float4 sx = nsx4[g];
    float4 sy = nsy4[g];

    float4 xo = x, yo = y, sxo = sx, syo = sy;

    if (i0 < NUM_MOVABLE) {
        {
            float r = g_ratio[bin_of(x.x + 0.5f * sx.x) * NB + bin_of(y.x + 0.5f * sy.x)];
            float sr = sqrtf(r * scale);
            float nx = sx.x * sr, ny = sy.x * sr;
            xo.x = x.x + 0.5f * (sx.x - nx); yo.x = y.x + 0.5f * (sy.x - ny);
            sxo.x = nx; syo.x = ny;
        }
        {
            float r = g_ratio[bin_of(x.y + 0.5f * sx.y) * NB + bin_of(y.y + 0.5f * sy.y)];
            float sr = sqrtf(r * scale);
            float nx = sx.y * sr, ny = sy.y * sr;
            xo.y = x.y + 0.5f * (sx.y - nx); yo.y = y.y + 0.5f * (sy.y - ny);
            sxo.y = nx; syo.y = ny;
        }
        {
            float r = g_ratio[bin_of(x.z + 0.5f * sx.z) * NB + bin_of(y.z + 0.5f * sy.z)];
            float sr = sqrtf(r * scale);
            float nx = sx.z * sr, ny = sy.z * sr;
            xo.z = x.z + 0.5f * (sx.z - nx); yo.z = y.z + 0.5f * (sy.z - ny);
            sxo.z = nx; syo.z = ny;
        }
        {
            float r = g_ratio[bin_of(x.w + 0.5f * sx.w) * NB + bin_of(y.w + 0.5f * sy.w)];
            float sr = sqrtf(r * scale);
            float nx = sx.w * sr, ny = sy.w * sr;
            xo.w = x.w + 0.5f * (sx.w - nx); yo.w = y.w + 0.5f * (sy.w - ny);
            sxo.w = nx; syo.w = ny;
        }
    } else if (i0 >= NUM_NODES - NUM_FILLER) {
        sxo.x = sx.x * fscale; sxo.y = sx.y * fscale;
        sxo.z = sx.z * fscale; sxo.w = sx.w * fscale;
        syo.x = sy.x * fscale; syo.y = sy.y * fscale;
        syo.z = sy.z * fscale; syo.w = sy.w * fscale;
    }

    const int Q = NUM_NODES / 4;
    out[g]         = xo;
    out[Q + g]     = yo;
    out[2 * Q + g] = sxo;
    out[3 * Q + g] = syo;
}

// ---------------- launch -----------------------------------------------------
extern "C" void kernel_launch(void* const* d_in, const int* in_sizes, int n_in,
                              void* d_out, int out_size) {
    const float* pos         = (const float*)d_in[0];
    const float* pin_pos     = (const float*)d_in[1];
    const float* node_size_x = (const float*)d_in[2];
    const float* node_size_y = (const float*)d_in[3];
    const int*   flat_netpin = (const int*)d_in[4];
    float* out = (float*)d_out;

    const float4* pos4  = (const float4*)pos;
    const float4* posy4 = (const float4*)(pos + NUM_NODES);
    const float4* nsx4  = (const float4*)node_size_x;
    const float4* nsy4  = (const float4*)node_size_y;
    const float4* px4   = (const float4*)pin_pos;
    const float4* py4   = (const float4*)(pin_pos + NUM_PINS);

    const int Q = NUM_NODES / 4;

    k_prep<<<(PIN_GROUPS + 255) / 256, 256>>>(px4, py4);
    k_fused<<<NET_BLOCKS + AREA_BLOCKS, 256>>>(flat_netpin,
                                               pos4, posy4, nsx4, nsy4);
    k_scan<<<NB, NB>>>();
    k_output<<<(Q + 255) / 256, 256>>>(pos4, posy4, nsx4, nsy4, (float4*)out);
}